// round 1
// baseline (speedup 1.0000x reference)
#include <cuda_runtime.h>
#include <cstdint>

// ---------------- problem constants ----------------
#define LROW   8192
#define LMASK  8191
#define TILE   249
#define NY     (TILE + 15)   // 264  Prim/y halo range
#define NH1    (TILE + 11)   // 260  h1 points
#define NH2    (TILE + 7)    // 256  h2 points == blockDim
#define NC     (TILE + 3)    // 252  coeff/grad points
#define NP1    260           // stride of h1/h2 rows (points per channel)
#define NTHREADS 256

// dynamic smem layout (float offsets)
#define OFF_W2   0            // 20480
#define OFF_H1   20480        // 64*260 = 16640
#define OFF_W1   37120        // 320
#define OFF_B1   37440        // 64
#define OFF_B2   37504        // 64
#define OFF_W3   37568        // 1280 (float4-aligned)
#define OFF_B3   38848        // 4
#define OFF_PRIM 38852        // 264
#define OFF_Y    39116        // 264
#define OFF_G    39380        // 252
#define OFF_PHI  39632        // 252
#define OFF_FLUX 39884        // 252
#define SMEM_FLOATS 40136
#define SMEM_BYTES  (SMEM_FLOATS * 4)

typedef unsigned long long ull;

__device__ float g_mn[4096];
__device__ float g_rs[4096];

__device__ __forceinline__ float tanha(float x) {
    float r; asm("tanh.approx.f32 %0, %1;" : "=f"(r) : "f"(x)); return r;
}
__device__ __forceinline__ ull pack2(float a, float b) {
    ull r; asm("mov.b64 %0, {%1, %2};" : "=l"(r) : "f"(a), "f"(b)); return r;
}
__device__ __forceinline__ void unpack2(ull v, float& a, float& b) {
    asm("mov.b64 {%0, %1}, %2;" : "=f"(a), "=f"(b) : "l"(v));
}
__device__ __forceinline__ void ffma2(ull& d, ull a, ull b) {
    asm("fma.rn.f32x2 %0, %1, %2, %0;" : "+l"(d) : "l"(a), "l"(b));
}

// ---------------- per-row min/max ----------------
__global__ void stats_kernel(const float* __restrict__ Prim) {
    __shared__ float smn[8], smx[8];
    const int row = blockIdx.x;
    const float4* p = (const float4*)(Prim + (size_t)row * LROW);
    float mn = 3.4e38f, mx = -3.4e38f;
    for (int i = threadIdx.x; i < LROW / 4; i += NTHREADS) {
        float4 v = p[i];
        mn = fminf(mn, fminf(fminf(v.x, v.y), fminf(v.z, v.w)));
        mx = fmaxf(mx, fmaxf(fmaxf(v.x, v.y), fmaxf(v.z, v.w)));
    }
    #pragma unroll
    for (int o = 16; o; o >>= 1) {
        mn = fminf(mn, __shfl_xor_sync(0xffffffffu, mn, o));
        mx = fmaxf(mx, __shfl_xor_sync(0xffffffffu, mx, o));
    }
    if ((threadIdx.x & 31) == 0) { smn[threadIdx.x >> 5] = mn; smx[threadIdx.x >> 5] = mx; }
    __syncthreads();
    if (threadIdx.x == 0) {
        #pragma unroll
        for (int i = 1; i < 8; i++) { mn = fminf(mn, smn[i]); mx = fmaxf(mx, smx[i]); }
        g_mn[row] = mn;
        g_rs[row] = 1.0f / fmaxf((mx - mn) * 0.5f, 1e-4f);
    }
}

// ---------------- fused main kernel ----------------
__global__ void __launch_bounds__(NTHREADS, 1)
fused_kernel(const float* __restrict__ Prim,
             const float* __restrict__ W1, const float* __restrict__ b1,
             const float* __restrict__ W2, const float* __restrict__ b2,
             const float* __restrict__ W3, const float* __restrict__ b3,
             float* __restrict__ Out)
{
    extern __shared__ float smem[];
    float* sW2   = smem + OFF_W2;
    float* sH1   = smem + OFF_H1;   // [64][NP1]; reused for h2 after conv2
    float* sW1   = smem + OFF_W1;
    float* sB1   = smem + OFF_B1;
    float* sB2   = smem + OFF_B2;
    float* sW3   = smem + OFF_W3;
    float* sB3   = smem + OFF_B3;
    float* sPrim = smem + OFF_PRIM;
    float* sY    = smem + OFF_Y;
    float* sGrad = smem + OFF_G;
    float* sPhi  = smem + OFF_PHI;
    float* sFlux = smem + OFF_FLUX;

    const int tid = threadIdx.x;
    const int row = blockIdx.y;
    const int t0  = blockIdx.x * TILE;
    const float* PR = Prim + (size_t)row * LROW;

    // ---- stage weights ----
    {
        const float4* gW2 = (const float4*)W2;
        float4* s4 = (float4*)sW2;
        #pragma unroll
        for (int i = 0; i < 20; i++) s4[tid + i * NTHREADS] = gW2[tid + i * NTHREADS];
        for (int i = tid; i < 320; i += NTHREADS) sW1[i] = W1[i];
        if (tid < 64) { sB1[tid] = b1[tid]; sB2[tid] = b2[tid]; }
        const float4* gW3 = (const float4*)W3;
        float4* sw34 = (float4*)sW3;
        for (int i = tid; i < 320; i += NTHREADS) sw34[i] = gW3[i];
        if (tid < 4) sB3[tid] = b3[tid];
    }
    // ---- stage Prim + rescale (periodic) ----
    const float mn = g_mn[row], rs = g_rs[row];
    for (int j = tid; j < NY; j += NTHREADS) {
        int l = (t0 + j - 8) & LMASK;
        float p = PR[l];
        sPrim[j] = p;
        sY[j] = (p - mn) * rs - 1.0f;
    }
    __syncthreads();

    // ---- conv1: y -> h1 [64][NH1], tanh ----
    for (int j1 = tid; j1 < NH1; j1 += NTHREADS) {
        float y0 = sY[j1], y1 = sY[j1 + 1], y2 = sY[j1 + 2], y3 = sY[j1 + 3], y4 = sY[j1 + 4];
        #pragma unroll 4
        for (int ci = 0; ci < 64; ci++) {
            float a = sB1[ci];
            a = fmaf(sW1[ci],        y0, a);
            a = fmaf(sW1[64  + ci],  y1, a);
            a = fmaf(sW1[128 + ci],  y2, a);
            a = fmaf(sW1[192 + ci],  y3, a);
            a = fmaf(sW1[256 + ci],  y4, a);
            sH1[ci * NP1 + j1] = tanha(a);
        }
    }
    __syncthreads();

    // ---- conv2: h1 -> h2 (64 co in packed f32x2 registers per thread) ----
    ull acc[32];
    #pragma unroll
    for (int c = 0; c < 32; c++) acc[c] = pack2(sB2[2 * c], sB2[2 * c + 1]);
    #pragma unroll
    for (int k = 0; k < 5; k++) {
        const float* hp = sH1 + tid + k;
        const ulonglong2* wk = (const ulonglong2*)(sW2 + k * 4096);
        #pragma unroll 2
        for (int ci = 0; ci < 64; ci++) {
            float h = hp[ci * NP1];
            ull hh = pack2(h, h);
            const ulonglong2* w = wk + ci * 16;
            #pragma unroll
            for (int q = 0; q < 16; q++) {
                ulonglong2 ww = w[q];
                ffma2(acc[2 * q],     hh, ww.x);
                ffma2(acc[2 * q + 1], hh, ww.y);
            }
        }
    }
    __syncthreads();   // all h1 reads done before overwrite
    #pragma unroll
    for (int c = 0; c < 32; c++) {
        float a, b; unpack2(acc[c], a, b);
        sH1[(2 * c)     * NP1 + tid] = tanha(a);
        sH1[(2 * c + 1) * NP1 + tid] = tanha(b);
    }
    __syncthreads();

    // ---- conv3 + alpha + grad ----
    if (tid < NC) {
        float c0 = sB3[0], c1 = sB3[1], c2 = sB3[2], c3 = sB3[3];
        #pragma unroll
        for (int k = 0; k < 5; k++) {
            const float* hp = sH1 + tid + k;
            const float4* w = ((const float4*)sW3) + k * 64;
            #pragma unroll 4
            for (int ci = 0; ci < 64; ci++) {
                float h = hp[ci * NP1];
                float4 ww = w[ci];
                c0 = fmaf(h, ww.x, c0);
                c1 = fmaf(h, ww.y, c1);
                c2 = fmaf(h, ww.z, c2);
                c3 = fmaf(h, ww.w, c3);
            }
        }
        // alpha = ALPHA_P + coeffs @ NULL_BASIS  (LAPACK LQ-Householder basis)
        const float S = c0 + c1 + c2 + c3;
        const float NB0 = 0.4472135954999579f;    // 1/sqrt(5)
        const float NBB = 0.1381966011250105f;    // (5 - sqrt(5))/20
        float a0 =  0.083333336f            - NB0 * S;
        float a1 = -0.66666669f  + c0       - NBB * S;
        float a2 =                 c1       - NBB * S;
        float a3 =  0.66666669f  + c2       - NBB * S;
        float a4 = -0.083333336f + c3       - NBB * S;
        // grad_x = (sum_k Prim[l+k-2]*alpha_k)/DX,  local Prim idx = tid+4+k
        float g = sPrim[tid + 4] * a0 + sPrim[tid + 5] * a1 + sPrim[tid + 6] * a2
                + sPrim[tid + 7] * a3 + sPrim[tid + 8] * a4;
        sGrad[tid] = g * 64.0f;
    }
    __syncthreads();

    // ---- TVD limiter phi ----
    if (tid >= 1 && tid <= TILE + 2) {
        float gc = sGrad[tid], gp = sGrad[tid - 1];
        float aa = (gc < 0.0f) ? -1.0f : 1.0f;
        float ri = gp / (fmaxf(fabsf(gc), 1e-15f) * aa);
        sPhi[tid] = (ri * ri + ri) / (ri * ri + 1.0f);
    }
    __syncthreads();

    // ---- Godunov-type flux ----
    if (tid >= 1 && tid <= TILE + 1) {
        float uL = sPrim[tid + 6] + 0.0078125f * sPhi[tid]     * sGrad[tid];       // 0.5*DX
        float uR = sPrim[tid + 7] - 0.0078125f * sPhi[tid + 1] * sGrad[tid + 1];
        sFlux[tid] = 0.25f * ((uL * uL + uR * uR) - fabsf(uL + uR) * (uR - uL));
    }
    __syncthreads();

    // ---- divergence + update ----
    {
        int l = t0 + tid;
        if (tid < TILE && l < LROW) {
            int o = tid + 2;
            Out[(size_t)row * LROW + l] = sPrim[tid + 8] - 0.01f * (sFlux[o] - sFlux[o - 1]);
        }
    }
}

// ---------------- launch ----------------
extern "C" void kernel_launch(void* const* d_in, const int* in_sizes, int n_in,
                              void* d_out, int out_size)
{
    const float* Prim = (const float*)d_in[0];
    const float* W1   = (const float*)d_in[1];
    const float* b1   = (const float*)d_in[2];
    const float* W2   = (const float*)d_in[3];
    const float* b2   = (const float*)d_in[4];
    const float* W3   = (const float*)d_in[5];
    const float* b3   = (const float*)d_in[6];
    float* Out = (float*)d_out;

    const int B = in_sizes[0] / LROW;

    cudaFuncSetAttribute(fused_kernel,
                         cudaFuncAttributeMaxDynamicSharedMemorySize, SMEM_BYTES);

    stats_kernel<<<B, NTHREADS>>>(Prim);

    dim3 grid((LROW + TILE - 1) / TILE, B);
    fused_kernel<<<grid, NTHREADS, SMEM_BYTES>>>(Prim, W1, b1, W2, b2, W3, b3, Out);
}

// round 2
// speedup vs baseline: 1.3970x; 1.3970x over previous
#include <cuda_runtime.h>
#include <cstdint>

// ---------------- problem constants ----------------
#define LROW   8192
#define LMASK  8191
#define TILE   505
#define NY     (TILE + 15)   // 520  Prim halo range
#define NH1    (TILE + 11)   // 516  h1 points
#define NH2    (TILE + 7)    // 512  h2 points (4 per thread)
#define NC     (TILE + 3)    // 508  coeff/grad points
#define NP1    516           // stride of h1/h2 channel rows
#define NTHREADS 256
#define NBLKX  17            // ceil(8192/505)

// dynamic smem layout (float offsets)
#define OFF_W2   0            // 20480
#define OFF_H1   20480        // 64*516 = 33024
#define OFF_W1   53504        // 320
#define OFF_B1   53824        // 64
#define OFF_B2   53888        // 64
#define OFF_W3   53952        // 1280 (16B aligned)
#define OFF_B3   55232        // 4
#define OFF_PRIM 55236        // 520
#define OFF_G    55756        // 508
#define OFF_PHI  56264        // 508
#define OFF_FLUX 56772        // 508
#define SMEM_FLOATS 57280
#define SMEM_BYTES  (SMEM_FLOATS * 4)   // 229120 <= 232448 opt-in max

typedef unsigned long long ull;

__device__ float g_mn[4096];
__device__ float g_rs[4096];

__device__ __forceinline__ float tanha(float x) {
    float r; asm("tanh.approx.f32 %0, %1;" : "=f"(r) : "f"(x)); return r;
}
__device__ __forceinline__ ull pack2(float a, float b) {
    ull r; asm("mov.b64 %0, {%1, %2};" : "=l"(r) : "f"(a), "f"(b)); return r;
}
__device__ __forceinline__ void unpack2(ull v, float& a, float& b) {
    asm("mov.b64 {%0, %1}, %2;" : "=f"(a), "=f"(b) : "l"(v));
}
__device__ __forceinline__ void ffma2(ull& d, ull a, ull b) {
    asm("fma.rn.f32x2 %0, %1, %2, %0;" : "+l"(d) : "l"(a), "l"(b));
}

// ---------------- per-row min/max ----------------
__global__ void stats_kernel(const float* __restrict__ Prim) {
    __shared__ float smn[8], smx[8];
    const int row = blockIdx.x;
    const float4* p = (const float4*)(Prim + (size_t)row * LROW);
    float mn = 3.4e38f, mx = -3.4e38f;
    for (int i = threadIdx.x; i < LROW / 4; i += NTHREADS) {
        float4 v = p[i];
        mn = fminf(mn, fminf(fminf(v.x, v.y), fminf(v.z, v.w)));
        mx = fmaxf(mx, fmaxf(fmaxf(v.x, v.y), fmaxf(v.z, v.w)));
    }
    #pragma unroll
    for (int o = 16; o; o >>= 1) {
        mn = fminf(mn, __shfl_xor_sync(0xffffffffu, mn, o));
        mx = fmaxf(mx, __shfl_xor_sync(0xffffffffu, mx, o));
    }
    if ((threadIdx.x & 31) == 0) { smn[threadIdx.x >> 5] = mn; smx[threadIdx.x >> 5] = mx; }
    __syncthreads();
    if (threadIdx.x == 0) {
        #pragma unroll
        for (int i = 1; i < 8; i++) { mn = fminf(mn, smn[i]); mx = fmaxf(mx, smx[i]); }
        g_mn[row] = mn;
        g_rs[row] = 1.0f / fmaxf((mx - mn) * 0.5f, 1e-4f);
    }
}

// ---------------- fused main kernel ----------------
__global__ void __launch_bounds__(NTHREADS, 1)
fused_kernel(const float* __restrict__ Prim,
             const float* __restrict__ W1, const float* __restrict__ b1,
             const float* __restrict__ W2, const float* __restrict__ b2,
             const float* __restrict__ W3, const float* __restrict__ b3,
             float* __restrict__ Out)
{
    extern __shared__ float smem[];
    float* sW2   = smem + OFF_W2;
    float* sH1   = smem + OFF_H1;   // [64][NP1]; reused for h2 after conv2
    float* sW1   = smem + OFF_W1;
    float* sB1   = smem + OFF_B1;
    float* sB2   = smem + OFF_B2;
    float* sW3   = smem + OFF_W3;
    float* sB3   = smem + OFF_B3;
    float* sPrim = smem + OFF_PRIM;
    float* sGrad = smem + OFF_G;
    float* sPhi  = smem + OFF_PHI;
    float* sFlux = smem + OFF_FLUX;

    const int tid = threadIdx.x;
    const int row = blockIdx.y;
    const int t0  = blockIdx.x * TILE;
    const float* PR = Prim + (size_t)row * LROW;

    // ---- stage weights ----
    {
        const float4* gW2 = (const float4*)W2;
        float4* s4 = (float4*)sW2;
        #pragma unroll
        for (int i = 0; i < 20; i++) s4[tid + i * NTHREADS] = gW2[tid + i * NTHREADS];
        for (int i = tid; i < 320; i += NTHREADS) sW1[i] = W1[i];
        if (tid < 64) { sB1[tid] = b1[tid]; sB2[tid] = b2[tid]; }
        const float4* gW3 = (const float4*)W3;
        float4* sw34 = (float4*)sW3;
        for (int i = tid; i < 320; i += NTHREADS) sw34[i] = gW3[i];
        if (tid < 4) sB3[tid] = b3[tid];
    }
    // ---- stage Prim (periodic) ----
    const float mn = g_mn[row], rs = g_rs[row];
    for (int j = tid; j < NY; j += NTHREADS) {
        sPrim[j] = PR[(t0 + j - 8) & LMASK];
    }
    __syncthreads();

    // ---- conv1: y -> h1 [64][NH1], tanh (y computed inline from Prim) ----
    for (int j1 = tid; j1 < NH1; j1 += NTHREADS) {
        float y0 = (sPrim[j1]     - mn) * rs - 1.0f;
        float y1 = (sPrim[j1 + 1] - mn) * rs - 1.0f;
        float y2 = (sPrim[j1 + 2] - mn) * rs - 1.0f;
        float y3 = (sPrim[j1 + 3] - mn) * rs - 1.0f;
        float y4 = (sPrim[j1 + 4] - mn) * rs - 1.0f;
        #pragma unroll 4
        for (int ci = 0; ci < 64; ci++) {
            float a = sB1[ci];
            a = fmaf(sW1[ci],        y0, a);
            a = fmaf(sW1[64  + ci],  y1, a);
            a = fmaf(sW1[128 + ci],  y2, a);
            a = fmaf(sW1[192 + ci],  y3, a);
            a = fmaf(sW1[256 + ci],  y4, a);
            sH1[ci * NP1 + j1] = tanha(a);
        }
    }
    __syncthreads();

    // ---- conv2: h1 -> h2 ; 4 points x 32 co per thread, f32x2 accumulators ----
    const int base = tid & 127;       // point base; points = base + 128*j
    const int coh  = tid >> 7;        // co half: 0 -> co[0:32), 1 -> co[32:64)
    ull acc[4][16];
    #pragma unroll
    for (int c = 0; c < 16; c++) {
        ull bv = pack2(sB2[coh * 32 + 2 * c], sB2[coh * 32 + 2 * c + 1]);
        acc[0][c] = bv; acc[1][c] = bv; acc[2][c] = bv; acc[3][c] = bv;
    }
    #pragma unroll
    for (int k = 0; k < 5; k++) {
        const float* hp = sH1 + k + base;
        const ulonglong2* wk = (const ulonglong2*)(sW2 + k * 4096 + coh * 32);
        #pragma unroll 1
        for (int ci = 0; ci < 64; ci++) {
            const float* h = hp + ci * NP1;
            float h0 = h[0], h1v = h[128], h2v = h[256], h3v = h[384];
            ull hh0 = pack2(h0, h0),  hh1 = pack2(h1v, h1v);
            ull hh2 = pack2(h2v, h2v), hh3 = pack2(h3v, h3v);
            const ulonglong2* w = wk + ci * 16;
            #pragma unroll
            for (int q = 0; q < 8; q++) {
                ulonglong2 ww = w[q];
                ffma2(acc[0][2 * q],     hh0, ww.x);
                ffma2(acc[0][2 * q + 1], hh0, ww.y);
                ffma2(acc[1][2 * q],     hh1, ww.x);
                ffma2(acc[1][2 * q + 1], hh1, ww.y);
                ffma2(acc[2][2 * q],     hh2, ww.x);
                ffma2(acc[2][2 * q + 1], hh2, ww.y);
                ffma2(acc[3][2 * q],     hh3, ww.x);
                ffma2(acc[3][2 * q + 1], hh3, ww.y);
            }
        }
    }
    __syncthreads();   // all h1 reads done before overwrite
    #pragma unroll
    for (int j = 0; j < 4; j++) {
        int p = base + 128 * j;
        #pragma unroll
        for (int c = 0; c < 16; c++) {
            float a, b; unpack2(acc[j][c], a, b);
            int co = coh * 32 + 2 * c;
            sH1[co * NP1 + p]       = tanha(a);
            sH1[(co + 1) * NP1 + p] = tanha(b);
        }
    }
    __syncthreads();

    // ---- conv3 + alpha + grad : 2 points per thread, f32x2 ----
    {
        const int jA = tid, jB = tid + 256;
        ull cA01 = pack2(sB3[0], sB3[1]), cA23 = pack2(sB3[2], sB3[3]);
        ull cB01 = cA01, cB23 = cA23;
        #pragma unroll
        for (int k = 0; k < 5; k++) {
            const float* hp = sH1 + k;
            const ulonglong2* w = ((const ulonglong2*)sW3) + k * 64;
            #pragma unroll 2
            for (int ci = 0; ci < 64; ci++) {
                float hA = hp[ci * NP1 + jA];
                float hB = hp[ci * NP1 + jB];
                ulonglong2 ww = w[ci];
                ull hhA = pack2(hA, hA), hhB = pack2(hB, hB);
                ffma2(cA01, hhA, ww.x);
                ffma2(cA23, hhA, ww.y);
                ffma2(cB01, hhB, ww.x);
                ffma2(cB23, hhB, ww.y);
            }
        }
        const float NB0 = 0.4472135954999579f;    // 1/sqrt(5)
        const float NBB = 0.1381966011250105f;    // (5 - sqrt(5))/20
        {
            float c0, c1, c2, c3;
            unpack2(cA01, c0, c1); unpack2(cA23, c2, c3);
            float S = c0 + c1 + c2 + c3;
            float a0 =  0.083333336f            - NB0 * S;
            float a1 = -0.66666669f  + c0       - NBB * S;
            float a2 =                 c1       - NBB * S;
            float a3 =  0.66666669f  + c2       - NBB * S;
            float a4 = -0.083333336f + c3       - NBB * S;
            float g = sPrim[jA + 4] * a0 + sPrim[jA + 5] * a1 + sPrim[jA + 6] * a2
                    + sPrim[jA + 7] * a3 + sPrim[jA + 8] * a4;
            sGrad[jA] = g * 64.0f;
        }
        if (jB < NC) {
            float c0, c1, c2, c3;
            unpack2(cB01, c0, c1); unpack2(cB23, c2, c3);
            float S = c0 + c1 + c2 + c3;
            float a0 =  0.083333336f            - NB0 * S;
            float a1 = -0.66666669f  + c0       - NBB * S;
            float a2 =                 c1       - NBB * S;
            float a3 =  0.66666669f  + c2       - NBB * S;
            float a4 = -0.083333336f + c3       - NBB * S;
            float g = sPrim[jB + 4] * a0 + sPrim[jB + 5] * a1 + sPrim[jB + 6] * a2
                    + sPrim[jB + 7] * a3 + sPrim[jB + 8] * a4;
            sGrad[jB] = g * 64.0f;
        }
    }
    __syncthreads();

    // ---- TVD limiter phi : valid j in [1, NC-1] ----
    for (int j = tid; j < NC; j += NTHREADS) {
        if (j >= 1) {
            float gc = sGrad[j], gp = sGrad[j - 1];
            float aa = (gc < 0.0f) ? -1.0f : 1.0f;
            float ri = gp / (fmaxf(fabsf(gc), 1e-15f) * aa);
            sPhi[j] = (ri * ri + ri) / (ri * ri + 1.0f);
        }
    }
    __syncthreads();

    // ---- Godunov-type flux : valid j in [1, TILE+1] ----
    for (int j = tid; j <= TILE + 1; j += NTHREADS) {
        if (j >= 1) {
            float uL = sPrim[j + 6] + 0.0078125f * sPhi[j]     * sGrad[j];
            float uR = sPrim[j + 7] - 0.0078125f * sPhi[j + 1] * sGrad[j + 1];
            sFlux[j] = 0.25f * ((uL * uL + uR * uR) - fabsf(uL + uR) * (uR - uL));
        }
    }
    __syncthreads();

    // ---- divergence + update ----
    for (int j = tid; j < TILE; j += NTHREADS) {
        int l = t0 + j;
        if (l < LROW) {
            Out[(size_t)row * LROW + l] =
                sPrim[j + 8] - 0.01f * (sFlux[j + 2] - sFlux[j + 1]);
        }
    }
}

// ---------------- launch ----------------
extern "C" void kernel_launch(void* const* d_in, const int* in_sizes, int n_in,
                              void* d_out, int out_size)
{
    const float* Prim = (const float*)d_in[0];
    const float* W1   = (const float*)d_in[1];
    const float* b1   = (const float*)d_in[2];
    const float* W2   = (const float*)d_in[3];
    const float* b2   = (const float*)d_in[4];
    const float* W3   = (const float*)d_in[5];
    const float* b3   = (const float*)d_in[6];
    float* Out = (float*)d_out;

    const int B = in_sizes[0] / LROW;

    cudaFuncSetAttribute(fused_kernel,
                         cudaFuncAttributeMaxDynamicSharedMemorySize, SMEM_BYTES);

    stats_kernel<<<B, NTHREADS>>>(Prim);

    dim3 grid(NBLKX, B);
    fused_kernel<<<grid, NTHREADS, SMEM_BYTES>>>(Prim, W1, b1, W2, b2, W3, b3, Out);
}